// round 3
// baseline (speedup 1.0000x reference)
#include <cuda_runtime.h>
#include <math.h>

#define BB 8
#define TT 256
#define UU 64
#define VV 512
#define U1 (UU + 1)
#define BSTRIDE 66          // padded blank row stride (bank-conflict-free on diagonals)
#define NEGF (-1e30f)

// Scratch (allocation-free rule: __device__ globals)
__device__ float g_blank[BB * TT * U1];   // log_probs[..., 0]
__device__ float g_emit [BB * TT * UU];   // log_probs[b,t,u,target[b,u]]
__device__ float g_loss [BB];

// ---------------------------------------------------------------------------
// Kernel 1: per-row logsumexp over V=512, emit blank/emit log-probs.
// One warp per (b,t,u) row; 16 floats/lane via 4x float4 -> single DRAM pass.
// ---------------------------------------------------------------------------
__global__ void __launch_bounds__(256) rnnt_softmax_kernel(
    const float* __restrict__ pred, const int* __restrict__ target)
{
    const int warp = (blockIdx.x * blockDim.x + threadIdx.x) >> 5;
    const int lane = threadIdx.x & 31;
    const int rows = BB * TT * U1;
    if (warp >= rows) return;

    const float4* row4 = reinterpret_cast<const float4*>(pred + (size_t)warp * VV);

    float4 v0 = row4[lane];
    float4 v1 = row4[lane + 32];
    float4 v2 = row4[lane + 64];
    float4 v3 = row4[lane + 96];

    // max
    float m = fmaxf(fmaxf(fmaxf(v0.x, v0.y), fmaxf(v0.z, v0.w)),
                    fmaxf(fmaxf(v1.x, v1.y), fmaxf(v1.z, v1.w)));
    m = fmaxf(m, fmaxf(fmaxf(fmaxf(v2.x, v2.y), fmaxf(v2.z, v2.w)),
                       fmaxf(fmaxf(v3.x, v3.y), fmaxf(v3.z, v3.w))));
    #pragma unroll
    for (int o = 16; o > 0; o >>= 1) m = fmaxf(m, __shfl_xor_sync(0xffffffffu, m, o));

    // sum of exp
    float s = 0.f;
    s += __expf(v0.x - m) + __expf(v0.y - m) + __expf(v0.z - m) + __expf(v0.w - m);
    s += __expf(v1.x - m) + __expf(v1.y - m) + __expf(v1.z - m) + __expf(v1.w - m);
    s += __expf(v2.x - m) + __expf(v2.y - m) + __expf(v2.z - m) + __expf(v2.w - m);
    s += __expf(v3.x - m) + __expf(v3.y - m) + __expf(v3.z - m) + __expf(v3.w - m);
    #pragma unroll
    for (int o = 16; o > 0; o >>= 1) s += __shfl_xor_sync(0xffffffffu, s, o);

    const float lse = m + logf(s);

    const int b   = warp / (TT * U1);
    const int rem = warp % (TT * U1);
    const int t   = rem / U1;
    const int u   = rem % U1;

    // blank = element 0 -> lane 0's v0.x
    if (lane == 0) g_blank[warp] = v0.x - lse;

    if (u < UU) {
        const int tgt = target[b * UU + u];
        float e = 0.f;
        const int base0 = 4 * lane;
        e += (base0 + 0   == tgt) ? v0.x : 0.f;
        e += (base0 + 1   == tgt) ? v0.y : 0.f;
        e += (base0 + 2   == tgt) ? v0.z : 0.f;
        e += (base0 + 3   == tgt) ? v0.w : 0.f;
        e += (base0 + 128 == tgt) ? v1.x : 0.f;
        e += (base0 + 129 == tgt) ? v1.y : 0.f;
        e += (base0 + 130 == tgt) ? v1.z : 0.f;
        e += (base0 + 131 == tgt) ? v1.w : 0.f;
        e += (base0 + 256 == tgt) ? v2.x : 0.f;
        e += (base0 + 257 == tgt) ? v2.y : 0.f;
        e += (base0 + 258 == tgt) ? v2.z : 0.f;
        e += (base0 + 259 == tgt) ? v2.w : 0.f;
        e += (base0 + 384 == tgt) ? v3.x : 0.f;
        e += (base0 + 385 == tgt) ? v3.y : 0.f;
        e += (base0 + 386 == tgt) ? v3.z : 0.f;
        e += (base0 + 387 == tgt) ? v3.w : 0.f;
        #pragma unroll
        for (int o = 16; o > 0; o >>= 1) e += __shfl_xor_sync(0xffffffffu, e, o);
        if (lane == 0) g_emit[b * TT * UU + t * UU + u] = e - lse;
    }
}

// ---------------------------------------------------------------------------
// logaddexp via MUFU only: x,y possibly ~ -1e30 sentinels (never both junk in
// valid region). mm + log(1 + exp(min-mm)); exp underflows to 0 for sentinel.
// ---------------------------------------------------------------------------
__device__ __forceinline__ float lae(float x, float y)
{
    const float mm = fmaxf(x, y);
    return mm + __logf(1.f + __expf(fminf(x, y) - mm));
}

// ---------------------------------------------------------------------------
// Kernel 2: warp-synchronous anti-diagonal wavefront DP. One warp per batch.
// lane owns u=lane (v1), u=lane+32 (v2); lane 0 also owns u=64 (v3).
// Neighbor (u-1) values of the previous diagonal arrive via 2 wrapped shfls.
// No __syncthreads in the loop; logaddexp is 2 MUFU ops.
// ---------------------------------------------------------------------------
__global__ void __launch_bounds__(128) rnnt_dp_kernel(
    const int* __restrict__ pred_len, const int* __restrict__ target_len)
{
    extern __shared__ float sm[];
    float* s_blank = sm;                   // TT * BSTRIDE floats (padded)
    float* s_emit  = sm + TT * BSTRIDE;    // TT * UU floats

    const int b   = blockIdx.x;
    const int tid = threadIdx.x;

    // Prefetch tiles with the whole block (128 threads)
    for (int i = tid; i < TT * U1; i += 128) {
        const int t = i / U1, u = i - t * U1;
        s_blank[t * BSTRIDE + u] = g_blank[b * TT * U1 + i];
    }
    for (int i = tid; i < TT * UU; i += 128)
        s_emit[i] = g_emit[b * TT * UU + i];
    __syncthreads();

    if (tid >= 32) return;
    const int lane = tid;
    const int pl = pred_len[b];
    const int tl = target_len[b];
    const float final_blank = s_blank[(pl - 1) * BSTRIDE + tl];

    const int u1 = lane;          // 0..31
    const int u2 = lane + 32;     // 32..63
    // lane 0 additionally owns u3 = 64

    float v1 = (lane == 0) ? 0.f : NEGF;   // diag 0: alpha[0][0] = 0
    float v2 = NEGF;
    float v3 = NEGF;

    const int src = (lane + 31) & 31;      // wrapped up-neighbor (lane0 <- lane31)

    for (int d = 1; d < TT + UU; ++d) {
        // previous-diagonal values at u-1
        const float a1 = __shfl_sync(0xffffffffu, v1, src);  // lane0 gets v1[31]=u31
        const float a2 = __shfl_sync(0xffffffffu, v2, src);  // lane0 gets v2[31]=u63

        // ---- cell (t1, u1) ----
        {
            const int t = d - u1;
            const int tc = min(max(t, 1), TT - 1);
            const float bl = s_blank[(tc - 1) * BSTRIDE + u1];
            const int tcc = min(max(t, 0), TT - 1);
            const float em = s_emit[tcc * UU + ((u1 > 0) ? (u1 - 1) : 0)];
            const float x = (t >= 1 && t < TT) ? (v1 + bl) : NEGF;
            const float pm = (lane == 0) ? NEGF : a1;
            const float y = (u1 > 0 && t >= 0 && t < TT) ? (pm + em) : NEGF;
            if (t >= 0 && t < TT) {
                v1 = lae(x, y);
                if (u1 == tl && t == pl - 1) g_loss[b] = v1 + final_blank;
            }
        }
        // ---- cell (t2, u2) ----
        {
            const int t = d - u2;
            const int tc = min(max(t, 1), TT - 1);
            const float bl = s_blank[(tc - 1) * BSTRIDE + u2];
            const int tcc = min(max(t, 0), TT - 1);
            const float em = s_emit[tcc * UU + (u2 - 1)];
            const float x = (t >= 1 && t < TT) ? (v2 + bl) : NEGF;
            const float pm = (lane == 0) ? a1 : a2;   // lane0: u=32 needs u=31 = v1[31]
            const float y = (t >= 0 && t < TT) ? (pm + em) : NEGF;
            if (t >= 0 && t < TT) {
                v2 = lae(x, y);
                if (u2 == tl && t == pl - 1) g_loss[b] = v2 + final_blank;
            }
        }
        // ---- cell (t3, 64), lane 0 only ----
        if (lane == 0) {
            const int t = d - 64;
            if (t >= 0 && t < TT) {
                const int tc = max(t, 1);
                const float bl = s_blank[(tc - 1) * BSTRIDE + 64];
                const float em = s_emit[t * UU + 63];
                const float x = (t >= 1) ? (v3 + bl) : NEGF;
                const float y = a2 + em;              // u=63 prev diag = v2[31]
                v3 = lae(x, y);
                if (64 == tl && t == pl - 1) g_loss[b] = v3 + final_blank;
            }
        }
    }
}

// ---------------------------------------------------------------------------
// Kernel 3: mean over batch -> scalar output
// ---------------------------------------------------------------------------
__global__ void rnnt_finalize_kernel(float* __restrict__ out)
{
    float s = 0.f;
    #pragma unroll
    for (int b = 0; b < BB; b++) s += g_loss[b];
    out[0] = -s / (float)BB;
}

extern "C" void kernel_launch(void* const* d_in, const int* in_sizes, int n_in,
                              void* d_out, int out_size)
{
    const float* pred       = (const float*)d_in[0];
    const int*   target     = (const int*)  d_in[1];
    const int*   pred_len   = (const int*)  d_in[2];
    const int*   target_len = (const int*)  d_in[3];
    float*       out        = (float*)      d_out;

    (void)in_sizes; (void)n_in; (void)out_size;

    const int rows   = BB * TT * U1;               // 133120 rows
    const int wpb    = 256 / 32;                   // 8 warps per block
    const int blocks = (rows + wpb - 1) / wpb;     // 16640

    const int smem_bytes = (TT * BSTRIDE + TT * UU) * (int)sizeof(float); // 133120 B
    cudaFuncSetAttribute(rnnt_dp_kernel,
                         cudaFuncAttributeMaxDynamicSharedMemorySize, smem_bytes);

    rnnt_softmax_kernel<<<blocks, 256>>>(pred, target);
    rnnt_dp_kernel<<<BB, 128, smem_bytes>>>(pred_len, target_len);
    rnnt_finalize_kernel<<<1, 1>>>(out);
}

// round 4
// speedup vs baseline: 1.5317x; 1.5317x over previous
#include <cuda_runtime.h>
#include <math.h>

#define BB 8
#define TT 256
#define UU 64
#define VV 512
#define U1 (UU + 1)
#define BSTRIDE 66            // padded blank row stride
#define GROWS 64              // guard rows before/after
#define BROWS (GROWS + TT + GROWS)   // 384
#define NEGF (-1e30f)

// Scratch (allocation-free rule: __device__ globals)
__device__ float g_blank[BB * TT * U1];   // log_probs[..., 0]
__device__ float g_emit [BB * TT * UU];   // log_probs[b,t,u,target[b,u]]
__device__ float g_loss [BB];

// ---------------------------------------------------------------------------
// Kernel 1: per-row logsumexp over V=512, emit blank/emit log-probs.
// One warp per (b,t,u) row; 16 floats/lane via 4x float4 -> single DRAM pass.
// ---------------------------------------------------------------------------
__global__ void __launch_bounds__(256) rnnt_softmax_kernel(
    const float* __restrict__ pred, const int* __restrict__ target)
{
    const int warp = (blockIdx.x * blockDim.x + threadIdx.x) >> 5;
    const int lane = threadIdx.x & 31;
    const int rows = BB * TT * U1;
    if (warp >= rows) return;

    const float4* row4 = reinterpret_cast<const float4*>(pred + (size_t)warp * VV);

    float4 v0 = row4[lane];
    float4 v1 = row4[lane + 32];
    float4 v2 = row4[lane + 64];
    float4 v3 = row4[lane + 96];

    float m = fmaxf(fmaxf(fmaxf(v0.x, v0.y), fmaxf(v0.z, v0.w)),
                    fmaxf(fmaxf(v1.x, v1.y), fmaxf(v1.z, v1.w)));
    m = fmaxf(m, fmaxf(fmaxf(fmaxf(v2.x, v2.y), fmaxf(v2.z, v2.w)),
                       fmaxf(fmaxf(v3.x, v3.y), fmaxf(v3.z, v3.w))));
    #pragma unroll
    for (int o = 16; o > 0; o >>= 1) m = fmaxf(m, __shfl_xor_sync(0xffffffffu, m, o));

    float s = 0.f;
    s += __expf(v0.x - m) + __expf(v0.y - m) + __expf(v0.z - m) + __expf(v0.w - m);
    s += __expf(v1.x - m) + __expf(v1.y - m) + __expf(v1.z - m) + __expf(v1.w - m);
    s += __expf(v2.x - m) + __expf(v2.y - m) + __expf(v2.z - m) + __expf(v2.w - m);
    s += __expf(v3.x - m) + __expf(v3.y - m) + __expf(v3.z - m) + __expf(v3.w - m);
    #pragma unroll
    for (int o = 16; o > 0; o >>= 1) s += __shfl_xor_sync(0xffffffffu, s, o);

    const float lse = m + logf(s);

    const int b   = warp / (TT * U1);
    const int rem = warp % (TT * U1);
    const int t   = rem / U1;
    const int u   = rem % U1;

    if (lane == 0) g_blank[warp] = v0.x - lse;

    if (u < UU) {
        const int tgt = target[b * UU + u];
        float e = 0.f;
        const int base0 = 4 * lane;
        e += (base0 + 0   == tgt) ? v0.x : 0.f;
        e += (base0 + 1   == tgt) ? v0.y : 0.f;
        e += (base0 + 2   == tgt) ? v0.z : 0.f;
        e += (base0 + 3   == tgt) ? v0.w : 0.f;
        e += (base0 + 128 == tgt) ? v1.x : 0.f;
        e += (base0 + 129 == tgt) ? v1.y : 0.f;
        e += (base0 + 130 == tgt) ? v1.z : 0.f;
        e += (base0 + 131 == tgt) ? v1.w : 0.f;
        e += (base0 + 256 == tgt) ? v2.x : 0.f;
        e += (base0 + 257 == tgt) ? v2.y : 0.f;
        e += (base0 + 258 == tgt) ? v2.z : 0.f;
        e += (base0 + 259 == tgt) ? v2.w : 0.f;
        e += (base0 + 384 == tgt) ? v3.x : 0.f;
        e += (base0 + 385 == tgt) ? v3.y : 0.f;
        e += (base0 + 386 == tgt) ? v3.z : 0.f;
        e += (base0 + 387 == tgt) ? v3.w : 0.f;
        #pragma unroll
        for (int o = 16; o > 0; o >>= 1) e += __shfl_xor_sync(0xffffffffu, e, o);
        if (lane == 0) g_emit[b * TT * UU + t * UU + u] = e - lse;
    }
}

// logaddexp via MUFU: mm + log(1 + exp(min-mm)); exp underflows exactly to 0
// for sentinel-vs-real pairs, so lae(NEGF, y) == y bit-exact.
__device__ __forceinline__ float lae(float x, float y)
{
    const float mm = fmaxf(x, y);
    return mm + __logf(1.f + __expf(fminf(x, y) - mm));
}

// ---------------------------------------------------------------------------
// Kernel 2: branch-free warp-synchronous wavefront DP. One warp per batch.
// Guard-padded smem tiles (64 zero rows before/after) let every lane run
// identical straight-line code on every diagonal; inactive cells hold ~NEGF.
// Addresses are pure pointer walks (ib += 66, ie += 64).
// ---------------------------------------------------------------------------
__global__ void __launch_bounds__(128) rnnt_dp_kernel(
    const int* __restrict__ pred_len, const int* __restrict__ target_len)
{
    extern __shared__ float sm[];
    float* s_blank = sm;                       // BROWS * BSTRIDE floats
    float* s_emit  = sm + BROWS * BSTRIDE;     // BROWS * UU floats

    const int b   = blockIdx.x;
    const int tid = threadIdx.x;

    // Zero guard regions
    for (int i = tid; i < GROWS * BSTRIDE; i += 128) {
        s_blank[i] = 0.f;
        s_blank[(GROWS + TT) * BSTRIDE + i] = 0.f;
    }
    for (int i = tid; i < GROWS * UU; i += 128) {
        s_emit[i] = 0.f;
        s_emit[(GROWS + TT) * UU + i] = 0.f;
    }
    // Center fills
    for (int i = tid; i < TT * U1; i += 128) {
        const int t = i / U1, u = i - t * U1;
        s_blank[(GROWS + t) * BSTRIDE + u] = g_blank[b * TT * U1 + i];
    }
    for (int i = tid; i < TT * UU; i += 128)
        s_emit[GROWS * UU + i] = g_emit[b * TT * UU + i];
    __syncthreads();

    if (tid >= 32) return;
    const int lane = tid;
    const int pl = pred_len[b];
    const int tl = target_len[b];
    const float final_blank = s_blank[(GROWS + pl - 1) * BSTRIDE + tl];

    const int u1 = lane;          // 0..31
    const int u2 = lane + 32;     // 32..63  (u=64 handled as cell3, lane0-valid)

    float v1 = (lane == 0) ? 0.f : NEGF;   // alpha[0][0] = 0 at diag 0
    float v2 = NEGF;
    float v3 = NEGF;

    const float yoff1 = (lane == 0) ? NEGF : 0.f;   // u=0 has no emit path
    const int   src   = (lane + 31) & 31;           // wrapped up-neighbor

    // capture diagonals (0 = never; loop starts at d=1)
    const int dcap1 = (tl == u1) ? (pl - 1 + tl) : 0;
    const int dcap2 = (tl == u2) ? (pl - 1 + tl) : 0;
    const int dcap3 = (lane == 0 && tl == UU) ? (pl - 1 + tl) : 0;
    float res1 = 0.f, res2 = 0.f, res3 = 0.f;

    // pointer walks (indices at d=1)
    int ib  = (GROWS - lane) * BSTRIDE + lane;             // blank row (d-u1-1), col u1
    int ie  = (GROWS + 1 - lane) * UU + lane - 1;          // emit  row (d-u1),   col u1-1
    int ib3 = (GROWS + 1 - 65) * BSTRIDE + 64;             // cell3 blank (uniform)
    int ie3 = (GROWS + 1 - 64) * UU + 63;                  // cell3 emit  (uniform)

    #pragma unroll 4
    for (int d = 1; d < TT + UU; ++d) {
        const float a1 = __shfl_sync(0xffffffffu, v1, src);  // prev-diag u1-1 (lane0: u=31)
        const float a2 = __shfl_sync(0xffffffffu, v2, src);  // prev-diag u2-1 (lane0: u=63)

        const float bl1 = s_blank[ib];
        const float em1 = s_emit [ie];
        const float bl2 = s_blank[ib - 32 * BSTRIDE + 32];
        const float em2 = s_emit [ie - 32 * UU + 32];
        const float bl3 = s_blank[ib3];
        const float em3 = s_emit [ie3];
        ib += BSTRIDE; ie += UU; ib3 += BSTRIDE; ie3 += UU;

        const float x1 = v1 + bl1;
        const float y1 = (a1 + em1) + yoff1;
        const float x2 = v2 + bl2;
        const float y2 = ((lane == 0) ? a1 : a2) + em2;   // lane0's u=32 needs u=31 = a1
        const float x3 = v3 + bl3;
        const float y3 = a2 + em3;                        // u=64 needs u=63 = a2 (lane0)

        v1 = lae(x1, y1);
        v2 = lae(x2, y2);
        v3 = lae(x3, y3);

        res1 = (d == dcap1) ? v1 : res1;
        res2 = (d == dcap2) ? v2 : res2;
        res3 = (d == dcap3) ? v3 : res3;
    }

    if (dcap1 != 0) g_loss[b] = res1 + final_blank;
    if (dcap2 != 0) g_loss[b] = res2 + final_blank;
    if (dcap3 != 0) g_loss[b] = res3 + final_blank;
}

// ---------------------------------------------------------------------------
// Kernel 3: mean over batch -> scalar output
// ---------------------------------------------------------------------------
__global__ void rnnt_finalize_kernel(float* __restrict__ out)
{
    float s = 0.f;
    #pragma unroll
    for (int b = 0; b < BB; b++) s += g_loss[b];
    out[0] = -s / (float)BB;
}

extern "C" void kernel_launch(void* const* d_in, const int* in_sizes, int n_in,
                              void* d_out, int out_size)
{
    const float* pred       = (const float*)d_in[0];
    const int*   target     = (const int*)  d_in[1];
    const int*   pred_len   = (const int*)  d_in[2];
    const int*   target_len = (const int*)  d_in[3];
    float*       out        = (float*)      d_out;

    (void)in_sizes; (void)n_in; (void)out_size;

    const int rows   = BB * TT * U1;               // 133120 rows
    const int wpb    = 256 / 32;                   // 8 warps per block
    const int blocks = (rows + wpb - 1) / wpb;     // 16640

    const int smem_bytes = (BROWS * BSTRIDE + BROWS * UU) * (int)sizeof(float); // 199680
    cudaFuncSetAttribute(rnnt_dp_kernel,
                         cudaFuncAttributeMaxDynamicSharedMemorySize, smem_bytes);

    rnnt_softmax_kernel<<<blocks, 256>>>(pred, target);
    rnnt_dp_kernel<<<BB, 128, smem_bytes>>>(pred_len, target_len);
    rnnt_finalize_kernel<<<1, 1>>>(out);
}

// round 7
// speedup vs baseline: 1.6657x; 1.0875x over previous
#include <cuda_runtime.h>
#include <math.h>

#define BB 8
#define TT 256
#define UU 64
#define VV 512
#define U1 (UU + 1)
#define BSTRIDE 66            // padded blank row stride
#define GROWS 64              // guard rows before/after
#define BROWS (GROWS + TT + GROWS)   // 384
#define NEGF (-1e30f)
#define LOG2E 1.4426950408889634f
#define LN2   0.6931471805599453f

// Scratch (allocation-free rule: __device__ globals). Log2 domain.
__device__ float g_blank[BB * TT * U1];   // log2_probs[..., 0]
__device__ float g_emit [BB * TT * UU];   // log2_probs[b,t,u,target[b,u]]
__device__ float g_loss [BB];             // log2-domain final alpha+blank

// ---------------------------------------------------------------------------
// Kernel 1: per-row logsumexp over V=512 -> blank/emit log2-probs.
// One warp per (b,t,u) row. Emit fetched by direct gather (L1 hit), not a
// select tree. __logf (fast) for the lse.
// ---------------------------------------------------------------------------
__global__ void __launch_bounds__(256) rnnt_softmax_kernel(
    const float* __restrict__ pred, const int* __restrict__ target)
{
    const int warp = (blockIdx.x * blockDim.x + threadIdx.x) >> 5;
    const int lane = threadIdx.x & 31;
    const int rows = BB * TT * U1;
    if (warp >= rows) return;

    const int b   = warp / (TT * U1);
    const int rem = warp % (TT * U1);
    const int t   = rem / U1;
    const int u   = rem % U1;

    const float* rowp = pred + (size_t)warp * VV;
    const float4* row4 = reinterpret_cast<const float4*>(rowp);

    // emit gather (issued early; independent of the bulk stream)
    const int tgt = (u < UU) ? target[b * UU + u] : 0;
    const float ev = __ldg(rowp + tgt);

    float4 v0 = row4[lane];
    float4 v1 = row4[lane + 32];
    float4 v2 = row4[lane + 64];
    float4 v3 = row4[lane + 96];

    float m = fmaxf(fmaxf(fmaxf(v0.x, v0.y), fmaxf(v0.z, v0.w)),
                    fmaxf(fmaxf(v1.x, v1.y), fmaxf(v1.z, v1.w)));
    m = fmaxf(m, fmaxf(fmaxf(fmaxf(v2.x, v2.y), fmaxf(v2.z, v2.w)),
                       fmaxf(fmaxf(v3.x, v3.y), fmaxf(v3.z, v3.w))));
    #pragma unroll
    for (int o = 16; o > 0; o >>= 1) m = fmaxf(m, __shfl_xor_sync(0xffffffffu, m, o));

    float s = 0.f;
    s += __expf(v0.x - m) + __expf(v0.y - m) + __expf(v0.z - m) + __expf(v0.w - m);
    s += __expf(v1.x - m) + __expf(v1.y - m) + __expf(v1.z - m) + __expf(v1.w - m);
    s += __expf(v2.x - m) + __expf(v2.y - m) + __expf(v2.z - m) + __expf(v2.w - m);
    s += __expf(v3.x - m) + __expf(v3.y - m) + __expf(v3.z - m) + __expf(v3.w - m);
    #pragma unroll
    for (int o = 16; o > 0; o >>= 1) s += __shfl_xor_sync(0xffffffffu, s, o);

    if (lane == 0) {
        const float lse = m + __logf(s);
        g_blank[warp] = (v0.x - lse) * LOG2E;
        if (u < UU)
            g_emit[b * TT * UU + t * UU + u] = (ev - lse) * LOG2E;
    }
}

// log2-domain logaddexp: mm + log2(1 + 2^(min-mm)); exp2 underflows exactly
// to 0 for sentinel-vs-real pairs, so lae2(NEGF, y) == y bit-exact.
__device__ __forceinline__ float lae2(float x, float y)
{
    const float mm = fmaxf(x, y);
    const float dd = fminf(x, y) - mm;
    return mm + __log2f(1.f + exp2f(dd));
}

// ---------------------------------------------------------------------------
// Kernel 2: branch-free warp-synchronous wavefront DP, one warp per batch.
// u=0 column precomputed as a prefix sum (s_cum). Lanes own u=lane+1 and
// u=lane+33. Guard-padded smem tiles; pure pointer-walk addressing.
// ---------------------------------------------------------------------------
__global__ void __launch_bounds__(128) rnnt_dp_kernel(
    const int* __restrict__ pred_len, const int* __restrict__ target_len)
{
    extern __shared__ float sm[];
    float* s_blank = sm;                       // BROWS * BSTRIDE floats
    float* s_emit  = sm + BROWS * BSTRIDE;     // BROWS * UU floats
    __shared__ float s_cum[320];               // alpha[t][0] (log2), padded

    const int b   = blockIdx.x;
    const int tid = threadIdx.x;

    // Zero guards + cum padding
    for (int i = tid; i < GROWS * BSTRIDE; i += 128) {
        s_blank[i] = 0.f;
        s_blank[(GROWS + TT) * BSTRIDE + i] = 0.f;
    }
    for (int i = tid; i < GROWS * UU; i += 128) {
        s_emit[i] = 0.f;
        s_emit[(GROWS + TT) * UU + i] = 0.f;
    }
    for (int i = tid; i < 320; i += 128) s_cum[i] = 0.f;
    // Center fills
    for (int i = tid; i < TT * U1; i += 128) {
        const int t = i / U1, u = i - t * U1;
        s_blank[(GROWS + t) * BSTRIDE + u] = g_blank[b * TT * U1 + i];
    }
    for (int i = tid; i < TT * UU; i += 128)
        s_emit[GROWS * UU + i] = g_emit[b * TT * UU + i];
    __syncthreads();

    if (tid >= 32) return;
    const int lane = tid;
    const int pl = pred_len[b];
    const int tl = target_len[b];
    const float final_blank = s_blank[(GROWS + pl - 1) * BSTRIDE + tl];

    // ---- u=0 column: exclusive prefix sum of blank[t][0] (warp scan) ----
    {
        float carry = 0.f;
        #pragma unroll
        for (int c = 0; c < 8; ++c) {
            const float bv = s_blank[(GROWS + c * 32 + lane) * BSTRIDE];
            float inc = bv;
            #pragma unroll
            for (int o = 1; o < 32; o <<= 1) {
                const float n = __shfl_up_sync(0xffffffffu, inc, o);
                if (lane >= o) inc += n;
            }
            s_cum[c * 32 + lane] = carry + inc - bv;   // exclusive
            carry += __shfl_sync(0xffffffffu, inc, 31);
        }
    }

    // ---- wavefront: u1 = lane+1, u2 = lane+33 ----
    float v1 = NEGF, v2 = NEGF;
    int ib = (GROWS - 1 - lane) * BSTRIDE + lane + 1;   // blank row t-1, col u1
    int ie = (GROWS - lane) * UU + lane;                // emit row t, col u1-1
    const int  src = (lane + 31) & 31;                  // wrapped up-neighbor
    const bool l0  = (lane == 0);

    const int  dmatch = (lane + 33 == tl) ? (pl - 1 + tl) : -1;  // tl in [56,64]
    float res2 = 0.f;

    #pragma unroll 4
    for (int d = 1; d < TT + UU; ++d) {
        const float a1 = __shfl_sync(0xffffffffu, v1, src);  // prev-diag u1-1 (lane0: u=32)
        const float a2 = __shfl_sync(0xffffffffu, v2, src);  // prev-diag u2-1
        const float cumv = s_cum[d - 1];                     // broadcast LDS

        const float bl1 = s_blank[ib];
        const float em1 = s_emit [ie];
        const float bl2 = s_blank[ib - 2080];  // -32*BSTRIDE + 32
        const float em2 = s_emit [ie - 2016];  // -32*UU + 32
        ib += BSTRIDE; ie += UU;

        const float x1 = v1 + bl1;
        const float y1 = (l0 ? cumv : a1) + em1;
        const float x2 = v2 + bl2;
        const float y2 = (l0 ? a1 : a2) + em2;   // lane0's u=33 needs u=32 = v1[31]

        v1 = lae2(x1, y1);
        v2 = lae2(x2, y2);

        res2 = (d == dmatch) ? v2 : res2;
    }

    if (dmatch >= 0) g_loss[b] = res2 + final_blank;
}

// ---------------------------------------------------------------------------
// Kernel 3: mean over batch -> scalar output (convert log2 -> ln)
// ---------------------------------------------------------------------------
__global__ void rnnt_finalize_kernel(float* __restrict__ out)
{
    float s = 0.f;
    #pragma unroll
    for (int b = 0; b < BB; b++) s += g_loss[b];
    out[0] = -s * (LN2 / (float)BB);
}

extern "C" void kernel_launch(void* const* d_in, const int* in_sizes, int n_in,
                              void* d_out, int out_size)
{
    const float* pred       = (const float*)d_in[0];
    const int*   target     = (const int*)  d_in[1];
    const int*   pred_len   = (const int*)  d_in[2];
    const int*   target_len = (const int*)  d_in[3];
    float*       out        = (float*)      d_out;

    (void)in_sizes; (void)n_in; (void)out_size;

    const int rows   = BB * TT * U1;               // 133120 rows
    const int wpb    = 256 / 32;                   // 8 warps per block
    const int blocks = (rows + wpb - 1) / wpb;     // 16640

    const int smem_bytes = (BROWS * BSTRIDE + BROWS * UU) * (int)sizeof(float); // 199680
    cudaFuncSetAttribute(rnnt_dp_kernel,
                         cudaFuncAttributeMaxDynamicSharedMemorySize, smem_bytes);

    rnnt_softmax_kernel<<<blocks, 256>>>(pred, target);
    rnnt_dp_kernel<<<BB, 128, smem_bytes>>>(pred_len, target_len);
    rnnt_finalize_kernel<<<1, 1>>>(out);
}

// round 8
// speedup vs baseline: 1.9041x; 1.1431x over previous
#include <cuda_runtime.h>
#include <math.h>

#define BB 8
#define TT 256
#define UU 64
#define VV 512
#define U1 (UU + 1)
#define BSTRIDE 66            // padded blank row stride
#define GROWS 64              // guard rows before/after
#define BROWS (GROWS + TT + GROWS)   // 384
#define NEGF (-1e30f)
#define LOG2E 1.4426950408889634f
#define LN2   0.6931471805599453f

// Scratch (allocation-free rule: __device__ globals). Log2 domain.
__device__ float g_blank[BB * TT * U1];   // log2_probs[..., 0]
__device__ float g_emit [BB * TT * UU];   // log2_probs[b,t,u,target[b,u]]
__device__ float g_loss [BB];             // log2-domain final alpha+blank

// Raw MUFU intrinsics (guaranteed single-instruction regardless of fast-math)
__device__ __forceinline__ float ex2_fast(float x)
{
    float r; asm("ex2.approx.ftz.f32 %0, %1;" : "=f"(r) : "f"(x)); return r;
}
__device__ __forceinline__ float lg2_fast(float x)
{
    float r; asm("lg2.approx.f32 %0, %1;" : "=f"(r) : "f"(x)); return r;
}

// ---------------------------------------------------------------------------
// Kernel 1: per-row logsumexp over V=512 -> blank/emit log2-probs.
// One warp per (b,t,u) row; emit via direct gather (L1 hit).
// ---------------------------------------------------------------------------
__global__ void __launch_bounds__(256) rnnt_softmax_kernel(
    const float* __restrict__ pred, const int* __restrict__ target)
{
    const int warp = (blockIdx.x * blockDim.x + threadIdx.x) >> 5;
    const int lane = threadIdx.x & 31;
    const int rows = BB * TT * U1;
    if (warp >= rows) return;

    const int b   = warp / (TT * U1);
    const int rem = warp % (TT * U1);
    const int t   = rem / U1;
    const int u   = rem % U1;

    const float* rowp = pred + (size_t)warp * VV;
    const float4* row4 = reinterpret_cast<const float4*>(rowp);

    // emit gather (issued early; independent of the bulk stream)
    const int tgt = (u < UU) ? target[b * UU + u] : 0;
    const float ev = __ldg(rowp + tgt);

    float4 v0 = row4[lane];
    float4 v1 = row4[lane + 32];
    float4 v2 = row4[lane + 64];
    float4 v3 = row4[lane + 96];

    float m = fmaxf(fmaxf(fmaxf(v0.x, v0.y), fmaxf(v0.z, v0.w)),
                    fmaxf(fmaxf(v1.x, v1.y), fmaxf(v1.z, v1.w)));
    m = fmaxf(m, fmaxf(fmaxf(fmaxf(v2.x, v2.y), fmaxf(v2.z, v2.w)),
                       fmaxf(fmaxf(v3.x, v3.y), fmaxf(v3.z, v3.w))));
    #pragma unroll
    for (int o = 16; o > 0; o >>= 1) m = fmaxf(m, __shfl_xor_sync(0xffffffffu, m, o));

    // sum of 2^((v-m)*log2e) -- one FMUL + EX2 per element
    float s = 0.f;
    s += ex2_fast((v0.x - m) * LOG2E) + ex2_fast((v0.y - m) * LOG2E)
       + ex2_fast((v0.z - m) * LOG2E) + ex2_fast((v0.w - m) * LOG2E);
    s += ex2_fast((v1.x - m) * LOG2E) + ex2_fast((v1.y - m) * LOG2E)
       + ex2_fast((v1.z - m) * LOG2E) + ex2_fast((v1.w - m) * LOG2E);
    s += ex2_fast((v2.x - m) * LOG2E) + ex2_fast((v2.y - m) * LOG2E)
       + ex2_fast((v2.z - m) * LOG2E) + ex2_fast((v2.w - m) * LOG2E);
    s += ex2_fast((v3.x - m) * LOG2E) + ex2_fast((v3.y - m) * LOG2E)
       + ex2_fast((v3.z - m) * LOG2E) + ex2_fast((v3.w - m) * LOG2E);
    #pragma unroll
    for (int o = 16; o > 0; o >>= 1) s += __shfl_xor_sync(0xffffffffu, s, o);

    if (lane == 0) {
        // lse2 = log2-domain logsumexp = m*log2e + log2(s)
        const float lse2 = m * LOG2E + lg2_fast(s);
        g_blank[warp] = v0.x * LOG2E - lse2;
        if (u < UU)
            g_emit[b * TT * UU + t * UU + u] = ev * LOG2E - lse2;
    }
}

// log2-domain logaddexp, pure MUFU: mm + log2(1 + 2^(min-mm)).
// ex2.approx.ftz underflows to exactly 0 for sentinel-vs-real pairs,
// so lae2(NEGF, y) == y bit-exact.
__device__ __forceinline__ float lae2(float x, float y)
{
    const float mm = fmaxf(x, y);
    const float dd = fminf(x, y) - mm;
    return mm + lg2_fast(1.f + ex2_fast(dd));
}

// ---------------------------------------------------------------------------
// Kernel 2: branch-free warp-synchronous wavefront DP, one warp per batch.
// u=0 column precomputed as a prefix sum (s_cum). Lanes own u=lane+1 and
// u=lane+33. Guard-padded smem tiles; pure pointer-walk addressing.
// ---------------------------------------------------------------------------
__global__ void __launch_bounds__(128) rnnt_dp_kernel(
    const int* __restrict__ pred_len, const int* __restrict__ target_len)
{
    extern __shared__ float sm[];
    float* s_blank = sm;                       // BROWS * BSTRIDE floats
    float* s_emit  = sm + BROWS * BSTRIDE;     // BROWS * UU floats
    __shared__ float s_cum[320];               // alpha[t][0] (log2), padded

    const int b   = blockIdx.x;
    const int tid = threadIdx.x;

    // Zero guards + cum padding
    for (int i = tid; i < GROWS * BSTRIDE; i += 128) {
        s_blank[i] = 0.f;
        s_blank[(GROWS + TT) * BSTRIDE + i] = 0.f;
    }
    for (int i = tid; i < GROWS * UU; i += 128) {
        s_emit[i] = 0.f;
        s_emit[(GROWS + TT) * UU + i] = 0.f;
    }
    for (int i = tid; i < 320; i += 128) s_cum[i] = 0.f;
    // Center fills: blank (scalar, padded stride), emit (vectorized float4)
    for (int i = tid; i < TT * U1; i += 128) {
        const int t = i / U1, u = i - t * U1;
        s_blank[(GROWS + t) * BSTRIDE + u] = g_blank[b * TT * U1 + i];
    }
    {
        const float4* src4 = reinterpret_cast<const float4*>(g_emit + b * TT * UU);
        float4* dst4 = reinterpret_cast<float4*>(s_emit + GROWS * UU);
        for (int i = tid; i < TT * UU / 4; i += 128) dst4[i] = src4[i];
    }
    __syncthreads();

    if (tid >= 32) return;
    const int lane = tid;
    const int pl = pred_len[b];
    const int tl = target_len[b];
    const float final_blank = s_blank[(GROWS + pl - 1) * BSTRIDE + tl];

    // ---- u=0 column: exclusive prefix sum of blank[t][0] (warp scan) ----
    {
        float carry = 0.f;
        #pragma unroll
        for (int c = 0; c < 8; ++c) {
            const float bv = s_blank[(GROWS + c * 32 + lane) * BSTRIDE];
            float inc = bv;
            #pragma unroll
            for (int o = 1; o < 32; o <<= 1) {
                const float n = __shfl_up_sync(0xffffffffu, inc, o);
                if (lane >= o) inc += n;
            }
            s_cum[c * 32 + lane] = carry + inc - bv;   // exclusive
            carry += __shfl_sync(0xffffffffu, inc, 31);
        }
    }

    // ---- wavefront: u1 = lane+1, u2 = lane+33 ----
    float v1 = NEGF, v2 = NEGF;
    int ib = (GROWS - 1 - lane) * BSTRIDE + lane + 1;   // blank row t-1, col u1
    int ie = (GROWS - lane) * UU + lane;                // emit row t, col u1-1
    const int  src = (lane + 31) & 31;                  // wrapped up-neighbor
    const bool l0  = (lane == 0);

    const int  dmatch = (lane + 33 == tl) ? (pl - 1 + tl) : -1;  // tl in [56,64]
    float res2 = 0.f;

    #pragma unroll 4
    for (int d = 1; d < TT + UU; ++d) {
        const float a1 = __shfl_sync(0xffffffffu, v1, src);  // prev-diag u1-1 (lane0: u=32)
        const float a2 = __shfl_sync(0xffffffffu, v2, src);  // prev-diag u2-1
        const float cumv = s_cum[d - 1];                     // broadcast LDS

        const float bl1 = s_blank[ib];
        const float em1 = s_emit [ie];
        const float bl2 = s_blank[ib - 2080];  // -32*BSTRIDE + 32
        const float em2 = s_emit [ie - 2016];  // -32*UU + 32
        ib += BSTRIDE; ie += UU;

        const float x1 = v1 + bl1;
        const float y1 = (l0 ? cumv : a1) + em1;
        const float x2 = v2 + bl2;
        const float y2 = (l0 ? a1 : a2) + em2;   // lane0's u=33 needs u=32 = v1[31]

        v1 = lae2(x1, y1);
        v2 = lae2(x2, y2);

        res2 = (d == dmatch) ? v2 : res2;
    }

    if (dmatch >= 0) g_loss[b] = res2 + final_blank;
}

// ---------------------------------------------------------------------------
// Kernel 3: mean over batch -> scalar output (convert log2 -> ln)
// ---------------------------------------------------------------------------
__global__ void rnnt_finalize_kernel(float* __restrict__ out)
{
    float s = 0.f;
    #pragma unroll
    for (int b = 0; b < BB; b++) s += g_loss[b];
    out[0] = -s * (LN2 / (float)BB);
}

extern "C" void kernel_launch(void* const* d_in, const int* in_sizes, int n_in,
                              void* d_out, int out_size)
{
    const float* pred       = (const float*)d_in[0];
    const int*   target     = (const int*)  d_in[1];
    const int*   pred_len   = (const int*)  d_in[2];
    const int*   target_len = (const int*)  d_in[3];
    float*       out        = (float*)      d_out;

    (void)in_sizes; (void)n_in; (void)out_size;

    const int rows   = BB * TT * U1;               // 133120 rows
    const int wpb    = 256 / 32;                   // 8 warps per block
    const int blocks = (rows + wpb - 1) / wpb;     // 16640

    const int smem_bytes = (BROWS * BSTRIDE + BROWS * UU) * (int)sizeof(float); // 199680
    cudaFuncSetAttribute(rnnt_dp_kernel,
                         cudaFuncAttributeMaxDynamicSharedMemorySize, smem_bytes);

    rnnt_softmax_kernel<<<blocks, 256>>>(pred, target);
    rnnt_dp_kernel<<<BB, 128, smem_bytes>>>(pred_len, target_len);
    rnnt_finalize_kernel<<<1, 1>>>(out);
}